// round 6
// baseline (speedup 1.0000x reference)
#include <cuda_runtime.h>
#include <math.h>

// Problem shape (fixed by reference): x is (32, 256, 64, 64) fp32.
#define BB 32
#define CC 256
#define HH 64
#define WW 64
#define HWN 4096            // H*W
#define STRIPS 8            // pass-1 strips per batch (512 hw positions each)
#define K1_THREADS 128      // 128 threads x float4 = 512 positions

// Scratch (device globals: allocation-free, graph-safe).
__device__ float g_partial[BB * STRIPS * CC];  // per-(b,strip,c) partial sums for mean
__device__ float g_chmax[BB * HWN];            // max over C per (b,hw)
__device__ float g_chsum[BB * HWN];            // sum over C per (b,hw)
__device__ float g_chw[BB * CC];               // sigmoid(conv1d(mean)) per (b,c)
__device__ float g_sp[BB * HWN];               // sigmoid(conv2d(...)+bias) per (b,hw)

// ---------------------------------------------------------------------------
// Pass 1: single sweep over x. Each block owns (b, 512-position hw strip).
// Loop over the 256 channels; per thread keep running max/sum for its 4 hw
// positions (registers), and per channel block-reduce the strip sum for the
// channel-mean via warp shuffles + per-warp smem slab (conflict-free STS).
// ---------------------------------------------------------------------------
__global__ __launch_bounds__(K1_THREADS) void k1_reduce(const float* __restrict__ x) {
    const int b = blockIdx.x >> 3;        // /STRIPS
    const int s = blockIdx.x & 7;
    const int t = threadIdx.x;
    const int lane = t & 31;
    const int wid  = t >> 5;              // 4 warps

    __shared__ float ps[4 * CC];          // per-warp per-channel partial sums

    const float4* __restrict__ x4 = (const float4*)x;
    const int off = s * 128 + t;          // float4 offset within a (b,c) plane

    float4 mx = make_float4(-INFINITY, -INFINITY, -INFINITY, -INFINITY);
    float4 sm = make_float4(0.f, 0.f, 0.f, 0.f);

    #pragma unroll 4
    for (int c = 0; c < CC; ++c) {
        float4 v = x4[(((size_t)(b * CC + c)) << 10) + off];
        mx.x = fmaxf(mx.x, v.x); mx.y = fmaxf(mx.y, v.y);
        mx.z = fmaxf(mx.z, v.z); mx.w = fmaxf(mx.w, v.w);
        sm.x += v.x; sm.y += v.y; sm.z += v.z; sm.w += v.w;
        float ts = (v.x + v.y) + (v.z + v.w);
        ts += __shfl_xor_sync(0xffffffffu, ts, 16);
        ts += __shfl_xor_sync(0xffffffffu, ts, 8);
        ts += __shfl_xor_sync(0xffffffffu, ts, 4);
        ts += __shfl_xor_sync(0xffffffffu, ts, 2);
        ts += __shfl_xor_sync(0xffffffffu, ts, 1);
        if (lane == 0) ps[wid * CC + c] = ts;
    }
    __syncthreads();

    // Combine the 4 warp partials -> per-(b,strip,c) partial for the mean.
    for (int c = t; c < CC; c += K1_THREADS) {
        g_partial[(b * STRIPS + s) * CC + c] =
            (ps[c] + ps[CC + c]) + (ps[2 * CC + c] + ps[3 * CC + c]);
    }

    // Channel max / channel sum for the spatial branch.
    const int o4 = (b << 10) + off;       // float4 index into (B,HW)
    ((float4*)g_chmax)[o4] = mx;
    ((float4*)g_chsum)[o4] = sm;
}

// ---------------------------------------------------------------------------
// Tiny kernel: finish mean, conv1d (k=5, zero pad 2 over C), sigmoid.
// One block per batch, thread == channel.
// ---------------------------------------------------------------------------
__global__ __launch_bounds__(CC) void k2_conv1d(const float* __restrict__ w1) {
    const int b = blockIdx.x;
    const int c = threadIdx.x;
    __shared__ float m[CC];

    float acc = 0.f;
    #pragma unroll
    for (int s = 0; s < STRIPS; ++s)
        acc += g_partial[(b * STRIPS + s) * CC + c];
    m[c] = acc * (1.0f / (float)HWN);
    __syncthreads();

    float y = 0.f;
    #pragma unroll
    for (int k = 0; k < 5; ++k) {
        int cc = c + k - 2;
        if (cc >= 0 && cc < CC) y += w1[k] * m[cc];
    }
    g_chw[b * CC + c] = 1.0f / (1.0f + expf(-y));
}

// ---------------------------------------------------------------------------
// conv2d 7x7 over [max_c, mean_c], pad 3, + bias, sigmoid.
// Block = (b, 16-row strip), smem halo tile 2 x 22 x 70.
// ---------------------------------------------------------------------------
__global__ __launch_bounds__(256) void k3_conv2d(const float* __restrict__ w2,
                                                 const float* __restrict__ b2) {
    const int b = blockIdx.x >> 2;
    const int strip = blockIdx.x & 3;
    const int row0 = strip << 4;          // 0,16,32,48
    const int t = threadIdx.x;

    __shared__ float sin_[2][22][70];
    __shared__ float sw[98];
    __shared__ float sbias;

    if (t < 98) sw[t] = w2[t];
    if (t == 0) sbias = b2[0];

    for (int i = t; i < 2 * 22 * 70; i += 256) {
        int p = i / 1540;
        int rem = i - p * 1540;
        int r = rem / 70;
        int cl = rem - r * 70;
        int gr = row0 + r - 3;
        int gc = cl - 3;
        float v = 0.f;
        if (gr >= 0 && gr < HH && gc >= 0 && gc < WW) {
            int gi = (b << 12) + (gr << 6) + gc;
            v = (p == 0) ? g_chmax[gi] : g_chsum[gi] * (1.0f / (float)CC);
        }
        sin_[p][r][cl] = v;
    }
    __syncthreads();

    const int oc = t & 63;
    const int r0 = t >> 6;                // 0..3
    #pragma unroll
    for (int q = 0; q < 4; ++q) {
        int row = r0 + (q << 2);          // 0..15 (local)
        float acc = sbias;
        #pragma unroll
        for (int p = 0; p < 2; ++p)
            #pragma unroll
            for (int i = 0; i < 7; ++i)
                #pragma unroll
                for (int j = 0; j < 7; ++j)
                    acc += sw[p * 49 + i * 7 + j] * sin_[p][row + i][oc + j];
        g_sp[(b << 12) + ((row0 + row) << 6) + oc] = 1.0f / (1.0f + expf(-acc));
    }
}

// ---------------------------------------------------------------------------
// Pass 2: out = x * (1 + ch_w[b,c] + sp[b,hw]).  One float4 per thread.
// sp is 512 KB total -> pure L2 hits; ch_w is warp-uniform.
// ---------------------------------------------------------------------------
__global__ __launch_bounds__(256) void k4_final(const float* __restrict__ x,
                                                float* __restrict__ out) {
    const size_t i = (size_t)blockIdx.x * blockDim.x + threadIdx.x;  // float4 idx
    const size_t e = i << 2;                                         // element idx
    const int b  = (int)(e >> 20);        // 256*4096 = 2^20 elems per batch
    const int c  = (int)((e >> 12) & 255);
    const int hq = (int)((e & 4095) >> 2);

    float4 v  = ((const float4*)x)[i];
    float4 sp = ((const float4*)g_sp)[(b << 10) + hq];
    float  cw = 1.0f + __ldg(&g_chw[b * CC + c]);

    float4 o;
    o.x = v.x * (cw + sp.x);
    o.y = v.y * (cw + sp.y);
    o.z = v.z * (cw + sp.z);
    o.w = v.w * (cw + sp.w);
    ((float4*)out)[i] = o;
}

// ---------------------------------------------------------------------------
extern "C" void kernel_launch(void* const* d_in, const int* in_sizes, int n_in,
                              void* d_out, int out_size) {
    (void)in_sizes; (void)n_in; (void)out_size;
    const float* x   = (const float*)d_in[0];   // (32,256,64,64) fp32
    const float* w1  = (const float*)d_in[1];   // (1,1,5)
    const float* w2  = (const float*)d_in[2];   // (1,2,7,7)
    const float* b2  = (const float*)d_in[3];   // (1,)
    float* out = (float*)d_out;

    k1_reduce<<<BB * STRIPS, K1_THREADS>>>(x);
    k2_conv1d<<<BB, CC>>>(w1);
    k3_conv2d<<<BB * 4, 256>>>(w2, b2);

    const size_t total_f4 = (size_t)BB * CC * HWN / 4;   // 8,388,608
    k4_final<<<(unsigned)(total_f4 / 256), 256>>>(x, out);
}

// round 10
// speedup vs baseline: 1.5145x; 1.5145x over previous
#include <cuda_runtime.h>
#include <math.h>

// Problem shape (fixed by reference): x is (32, 256, 64, 64) fp32.
#define BB 32
#define CC 256
#define HH 64
#define WW 64
#define HWN 4096            // H*W
#define STRIPS 8            // pass-1 strips per batch (512 hw positions each)

// Scratch (device globals: allocation-free, graph-safe).
__device__ float g_partial[BB * STRIPS * CC];  // per-(b,strip,c) partial sums for mean
__device__ float g_chmax[BB * HWN];            // max over C per (b,hw)
__device__ float g_chsum[BB * HWN];            // sum over C per (b,hw)
__device__ float g_chw[BB * CC];               // sigmoid(conv1d(mean)) per (b,c)
__device__ float g_sp[BB * HWN];               // sigmoid(conv2d(...)+bias) per (b,hw)

// ---------------------------------------------------------------------------
// Pass 1: single sweep over x.  Block = (b, 512-position hw strip), 256 thr.
// Warp w owns channels [32w, 32w+32).  Per channel each thread loads 4
// independent float4 (double-buffered -> MLP 8), keeps per-hw running
// max/sum in registers, and does ONE 5-step shuffle reduce per channel
// (per 512 elements) for the channel-mean partial.  Cross-warp hw combine
// happens once at the end through a 16 KB smem slab.
// ---------------------------------------------------------------------------
__global__ __launch_bounds__(256) void k1_reduce(const float* __restrict__ x) {
    const int b    = blockIdx.x >> 3;
    const int s    = blockIdx.x & 7;
    const int t    = threadIdx.x;
    const int lane = t & 31;
    const int w    = t >> 5;              // 8 warps

    __shared__ float4 sred[8][128];       // 16 KB, reused (max pass, then sum pass)

    // base: start of this (b, strip) in float4 units
    const float4* __restrict__ x4 =
        (const float4*)x + (((size_t)b) << 18) + (s * 128);

    float4 mx[4], sm[4];
    #pragma unroll
    for (int j = 0; j < 4; ++j) {
        mx[j] = make_float4(-INFINITY, -INFINITY, -INFINITY, -INFINITY);
        sm[j] = make_float4(0.f, 0.f, 0.f, 0.f);
    }

    const int cbase = w * 32;

    // prefetch channel cbase
    float4 va[4];
    {
        const float4* p = x4 + (((size_t)cbase) << 10);
        #pragma unroll
        for (int j = 0; j < 4; ++j) va[j] = p[lane + 32 * j];
    }

    #pragma unroll 4
    for (int k = 0; k < 32; ++k) {
        // prefetch next channel (clamped: last iter re-loads same line, L1 hit)
        float4 vb[4];
        {
            int cn = cbase + (k < 31 ? k + 1 : 31);
            const float4* p = x4 + (((size_t)cn) << 10);
            #pragma unroll
            for (int j = 0; j < 4; ++j) vb[j] = p[lane + 32 * j];
        }

        float ts = 0.f;
        #pragma unroll
        for (int j = 0; j < 4; ++j) {
            mx[j].x = fmaxf(mx[j].x, va[j].x); mx[j].y = fmaxf(mx[j].y, va[j].y);
            mx[j].z = fmaxf(mx[j].z, va[j].z); mx[j].w = fmaxf(mx[j].w, va[j].w);
            sm[j].x += va[j].x; sm[j].y += va[j].y;
            sm[j].z += va[j].z; sm[j].w += va[j].w;
            ts += (va[j].x + va[j].y) + (va[j].z + va[j].w);
        }
        ts += __shfl_xor_sync(0xffffffffu, ts, 16);
        ts += __shfl_xor_sync(0xffffffffu, ts, 8);
        ts += __shfl_xor_sync(0xffffffffu, ts, 4);
        ts += __shfl_xor_sync(0xffffffffu, ts, 2);
        ts += __shfl_xor_sync(0xffffffffu, ts, 1);
        if (lane == 0)
            g_partial[(b * STRIPS + s) * CC + cbase + k] = ts;

        #pragma unroll
        for (int j = 0; j < 4; ++j) va[j] = vb[j];
    }

    // ---- cross-warp combine: max over C for each of the 128 f4 positions ----
    #pragma unroll
    for (int j = 0; j < 4; ++j) sred[w][lane + 32 * j] = mx[j];
    __syncthreads();
    if (t < 128) {
        float4 r = sred[0][t];
        #pragma unroll
        for (int ww = 1; ww < 8; ++ww) {
            float4 q = sred[ww][t];
            r.x = fmaxf(r.x, q.x); r.y = fmaxf(r.y, q.y);
            r.z = fmaxf(r.z, q.z); r.w = fmaxf(r.w, q.w);
        }
        ((float4*)g_chmax)[(b << 10) + s * 128 + t] = r;
    }
    __syncthreads();

    // ---- cross-warp combine: sum over C ----
    #pragma unroll
    for (int j = 0; j < 4; ++j) sred[w][lane + 32 * j] = sm[j];
    __syncthreads();
    if (t < 128) {
        float4 r = sred[0][t];
        #pragma unroll
        for (int ww = 1; ww < 8; ++ww) {
            float4 q = sred[ww][t];
            r.x += q.x; r.y += q.y; r.z += q.z; r.w += q.w;
        }
        ((float4*)g_chsum)[(b << 10) + s * 128 + t] = r;
    }
}

// ---------------------------------------------------------------------------
// Tiny kernel: finish mean, conv1d (k=5, zero pad 2 over C), sigmoid.
// One block per batch, thread == channel.
// ---------------------------------------------------------------------------
__global__ __launch_bounds__(CC) void k2_conv1d(const float* __restrict__ w1) {
    const int b = blockIdx.x;
    const int c = threadIdx.x;
    __shared__ float m[CC];

    float acc = 0.f;
    #pragma unroll
    for (int s = 0; s < STRIPS; ++s)
        acc += g_partial[(b * STRIPS + s) * CC + c];
    m[c] = acc * (1.0f / (float)HWN);
    __syncthreads();

    float y = 0.f;
    #pragma unroll
    for (int k = 0; k < 5; ++k) {
        int cc = c + k - 2;
        if (cc >= 0 && cc < CC) y += w1[k] * m[cc];
    }
    g_chw[b * CC + c] = 1.0f / (1.0f + expf(-y));
}

// ---------------------------------------------------------------------------
// conv2d 7x7 over [max_c, mean_c], pad 3, + bias, sigmoid.
// Block = (b, 16-row strip), smem halo tile 2 x 22 x 70.
// ---------------------------------------------------------------------------
__global__ __launch_bounds__(256) void k3_conv2d(const float* __restrict__ w2,
                                                 const float* __restrict__ b2) {
    const int b = blockIdx.x >> 2;
    const int strip = blockIdx.x & 3;
    const int row0 = strip << 4;          // 0,16,32,48
    const int t = threadIdx.x;

    __shared__ float sin_[2][22][70];
    __shared__ float sw[98];
    __shared__ float sbias;

    if (t < 98) sw[t] = w2[t];
    if (t == 0) sbias = b2[0];

    for (int i = t; i < 2 * 22 * 70; i += 256) {
        int p = i / 1540;
        int rem = i - p * 1540;
        int r = rem / 70;
        int cl = rem - r * 70;
        int gr = row0 + r - 3;
        int gc = cl - 3;
        float v = 0.f;
        if (gr >= 0 && gr < HH && gc >= 0 && gc < WW) {
            int gi = (b << 12) + (gr << 6) + gc;
            v = (p == 0) ? g_chmax[gi] : g_chsum[gi] * (1.0f / (float)CC);
        }
        sin_[p][r][cl] = v;
    }
    __syncthreads();

    const int oc = t & 63;
    const int r0 = t >> 6;                // 0..3
    #pragma unroll
    for (int q = 0; q < 4; ++q) {
        int row = r0 + (q << 2);          // 0..15 (local)
        float acc = sbias;
        #pragma unroll
        for (int p = 0; p < 2; ++p)
            #pragma unroll
            for (int i = 0; i < 7; ++i)
                #pragma unroll
                for (int j = 0; j < 7; ++j)
                    acc += sw[p * 49 + i * 7 + j] * sin_[p][row + i][oc + j];
        g_sp[(b << 12) + ((row0 + row) << 6) + oc] = 1.0f / (1.0f + expf(-acc));
    }
}

// ---------------------------------------------------------------------------
// Pass 2: out = x * (1 + ch_w[b,c] + sp[b,hw]).  Two float4 per thread for
// MLP; sp (512 KB) stays L2-resident; ch_w is warp-uniform.
// ---------------------------------------------------------------------------
__global__ __launch_bounds__(256) void k4_final(const float* __restrict__ x,
                                                float* __restrict__ out) {
    const size_t base = ((size_t)blockIdx.x * blockDim.x + threadIdx.x) * 2;
    #pragma unroll
    for (int u = 0; u < 2; ++u) {
        const size_t i = base + u;            // float4 idx
        const size_t e = i << 2;              // element idx
        const int b  = (int)(e >> 20);        // 2^20 elems per batch
        const int c  = (int)((e >> 12) & 255);
        const int hq = (int)((e & 4095) >> 2);

        float4 v  = ((const float4*)x)[i];
        float4 sp = ((const float4*)g_sp)[(b << 10) + hq];
        float  cw = 1.0f + __ldg(&g_chw[b * CC + c]);

        float4 o;
        o.x = v.x * (cw + sp.x);
        o.y = v.y * (cw + sp.y);
        o.z = v.z * (cw + sp.z);
        o.w = v.w * (cw + sp.w);
        ((float4*)out)[i] = o;
    }
}

// ---------------------------------------------------------------------------
extern "C" void kernel_launch(void* const* d_in, const int* in_sizes, int n_in,
                              void* d_out, int out_size) {
    (void)in_sizes; (void)n_in; (void)out_size;
    const float* x   = (const float*)d_in[0];   // (32,256,64,64) fp32
    const float* w1  = (const float*)d_in[1];   // (1,1,5)
    const float* w2  = (const float*)d_in[2];   // (1,2,7,7)
    const float* b2  = (const float*)d_in[3];   // (1,)
    float* out = (float*)d_out;

    k1_reduce<<<BB * STRIPS, 256>>>(x);
    k2_conv1d<<<BB, CC>>>(w1);
    k3_conv2d<<<BB * 4, 256>>>(w2, b2);

    const size_t total_f4 = (size_t)BB * CC * HWN / 4;   // 8,388,608
    k4_final<<<(unsigned)(total_f4 / 512), 256>>>(x, out);
}

// round 14
// speedup vs baseline: 1.5213x; 1.0044x over previous
#include <cuda_runtime.h>
#include <math.h>

// Problem shape (fixed by reference): x is (32, 256, 64, 64) fp32.
#define BB 32
#define CC 256
#define HH 64
#define WW 64
#define HWN 4096            // H*W
#define STRIPS 8            // pass-1 strips per batch (512 hw positions each)

// Scratch (device globals: allocation-free, graph-safe).
__device__ float g_pl[BB * STRIPS * CC * 32];  // per-(b,strip,c,lane) partials (8 MB)
__device__ float g_chmax[BB * HWN];            // max over C per (b,hw)
__device__ float g_chsum[BB * HWN];            // sum over C per (b,hw)
__device__ float g_chw[BB * CC];               // sigmoid(conv1d(mean)) per (b,c)
__device__ float g_sp[BB * HWN];               // sigmoid(conv2d(...)+bias) per (b,hw)

// ---------------------------------------------------------------------------
// Pass 1: single sweep over x.  Block = (b, 512-position hw strip), 256 thr.
// Warp w owns channels [32w, 32w+32).  Per channel each thread loads 4
// independent float4 (double-buffered), keeps per-hw running max/sum in
// registers, and writes its OWN scalar channel-partial to g_pl (coalesced
// 128 B per warp) — no shuffles in the hot loop, so the body is pure
// LDG/FADD/STG and pipelines to the BW roofline.  Cross-warp hw combine
// happens once at the end through a 16 KB smem slab.
// ---------------------------------------------------------------------------
__global__ __launch_bounds__(256) void k1_reduce(const float* __restrict__ x) {
    const int b    = blockIdx.x >> 3;
    const int s    = blockIdx.x & 7;
    const int t    = threadIdx.x;
    const int lane = t & 31;
    const int w    = t >> 5;              // 8 warps

    __shared__ float4 sred[8][128];       // 16 KB, reused (max pass, then sum pass)

    const float4* __restrict__ x4 =
        (const float4*)x + (((size_t)b) << 18) + (s * 128);

    float4 mx[4], sm[4];
    #pragma unroll
    for (int j = 0; j < 4; ++j) {
        mx[j] = make_float4(-INFINITY, -INFINITY, -INFINITY, -INFINITY);
        sm[j] = make_float4(0.f, 0.f, 0.f, 0.f);
    }

    const int cbase = w * 32;
    // per-(b,s,c,lane) scratch base for this warp
    float* __restrict__ pl = g_pl + ((size_t)(blockIdx.x * CC + cbase) << 5) + lane;

    // prefetch channel cbase
    float4 va[4];
    {
        const float4* p = x4 + (((size_t)cbase) << 10);
        #pragma unroll
        for (int j = 0; j < 4; ++j) va[j] = p[lane + 32 * j];
    }

    #pragma unroll 4
    for (int k = 0; k < 32; ++k) {
        // prefetch next channel (clamped: last iter re-loads same line, L1 hit)
        float4 vb[4];
        {
            int cn = cbase + (k < 31 ? k + 1 : 31);
            const float4* p = x4 + (((size_t)cn) << 10);
            #pragma unroll
            for (int j = 0; j < 4; ++j) vb[j] = p[lane + 32 * j];
        }

        float ts = 0.f;
        #pragma unroll
        for (int j = 0; j < 4; ++j) {
            mx[j].x = fmaxf(mx[j].x, va[j].x); mx[j].y = fmaxf(mx[j].y, va[j].y);
            mx[j].z = fmaxf(mx[j].z, va[j].z); mx[j].w = fmaxf(mx[j].w, va[j].w);
            sm[j].x += va[j].x; sm[j].y += va[j].y;
            sm[j].z += va[j].z; sm[j].w += va[j].w;
            ts += (va[j].x + va[j].y) + (va[j].z + va[j].w);
        }
        pl[(size_t)k << 5] = ts;          // coalesced 128 B store per warp

        #pragma unroll
        for (int j = 0; j < 4; ++j) va[j] = vb[j];
    }

    // ---- cross-warp combine: max over C for each of the 128 f4 positions ----
    #pragma unroll
    for (int j = 0; j < 4; ++j) sred[w][lane + 32 * j] = mx[j];
    __syncthreads();
    if (t < 128) {
        float4 r = sred[0][t];
        #pragma unroll
        for (int ww = 1; ww < 8; ++ww) {
            float4 q = sred[ww][t];
            r.x = fmaxf(r.x, q.x); r.y = fmaxf(r.y, q.y);
            r.z = fmaxf(r.z, q.z); r.w = fmaxf(r.w, q.w);
        }
        ((float4*)g_chmax)[(b << 10) + s * 128 + t] = r;
    }
    __syncthreads();

    // ---- cross-warp combine: sum over C ----
    #pragma unroll
    for (int j = 0; j < 4; ++j) sred[w][lane + 32 * j] = sm[j];
    __syncthreads();
    if (t < 128) {
        float4 r = sred[0][t];
        #pragma unroll
        for (int ww = 1; ww < 8; ++ww) {
            float4 q = sred[ww][t];
            r.x += q.x; r.y += q.y; r.z += q.z; r.w += q.w;
        }
        ((float4*)g_chsum)[(b << 10) + s * 128 + t] = r;
    }
}

// ---------------------------------------------------------------------------
// Merged tiny kernel.  Blocks 0..127: conv2d 7x7 over [max_c, mean_c] with
// smem halo tile.  Blocks 128..159: finish mean (sum g_pl), conv1d k=5 over
// channels, sigmoid.  The two halves are data-independent (both depend only
// on k1), so one launch covers both.
// ---------------------------------------------------------------------------
__global__ __launch_bounds__(256) void k23_small(const float* __restrict__ w1,
                                                 const float* __restrict__ w2,
                                                 const float* __restrict__ b2) {
    const int t = threadIdx.x;

    if (blockIdx.x >= 128) {
        // ---------------- conv1d branch: one block per batch ----------------
        const int b = blockIdx.x - 128;
        const int c = t;                  // 256 threads == 256 channels
        __shared__ float m[CC];

        float acc = 0.f;
        #pragma unroll
        for (int s = 0; s < STRIPS; ++s) {
            const float4* p = (const float4*)(g_pl + ((size_t)((b * STRIPS + s) * CC + c) << 5));
            #pragma unroll
            for (int q = 0; q < 8; ++q) {
                float4 v = p[q];
                acc += (v.x + v.y) + (v.z + v.w);
            }
        }
        m[c] = acc * (1.0f / (float)HWN);
        __syncthreads();

        float y = 0.f;
        #pragma unroll
        for (int k = 0; k < 5; ++k) {
            int cc = c + k - 2;
            if (cc >= 0 && cc < CC) y += w1[k] * m[cc];
        }
        g_chw[b * CC + c] = 1.0f / (1.0f + expf(-y));
        return;
    }

    // ---------------- conv2d branch: (b, 16-row strip) ----------------
    const int b = blockIdx.x >> 2;
    const int strip = blockIdx.x & 3;
    const int row0 = strip << 4;          // 0,16,32,48

    __shared__ float sin_[2][22][70];
    __shared__ float sw[98];
    __shared__ float sbias;

    if (t < 98) sw[t] = w2[t];
    if (t == 0) sbias = b2[0];

    for (int i = t; i < 2 * 22 * 70; i += 256) {
        int p = i / 1540;
        int rem = i - p * 1540;
        int r = rem / 70;
        int cl = rem - r * 70;
        int gr = row0 + r - 3;
        int gc = cl - 3;
        float v = 0.f;
        if (gr >= 0 && gr < HH && gc >= 0 && gc < WW) {
            int gi = (b << 12) + (gr << 6) + gc;
            v = (p == 0) ? g_chmax[gi] : g_chsum[gi] * (1.0f / (float)CC);
        }
        sin_[p][r][cl] = v;
    }
    __syncthreads();

    const int oc = t & 63;
    const int r0 = t >> 6;                // 0..3
    #pragma unroll
    for (int q = 0; q < 4; ++q) {
        int row = r0 + (q << 2);          // 0..15 (local)
        float acc = sbias;
        #pragma unroll
        for (int p = 0; p < 2; ++p)
            #pragma unroll
            for (int i = 0; i < 7; ++i)
                #pragma unroll
                for (int j = 0; j < 7; ++j)
                    acc += sw[p * 49 + i * 7 + j] * sin_[p][row + i][oc + j];
        g_sp[(b << 12) + ((row0 + row) << 6) + oc] = 1.0f / (1.0f + expf(-acc));
    }
}

// ---------------------------------------------------------------------------
// Pass 2: out = x * (1 + ch_w[b,c] + sp[b,hw]).  One float4 per thread
// (the 2-per-thread variant measured SLOWER: 44.35 vs 40.35 us).
// sp is 512 KB total -> pure L2 hits; ch_w is warp-uniform.
// ---------------------------------------------------------------------------
__global__ __launch_bounds__(256) void k4_final(const float* __restrict__ x,
                                                float* __restrict__ out) {
    const size_t i = (size_t)blockIdx.x * blockDim.x + threadIdx.x;  // float4 idx
    const size_t e = i << 2;                                         // element idx
    const int b  = (int)(e >> 20);        // 256*4096 = 2^20 elems per batch
    const int c  = (int)((e >> 12) & 255);
    const int hq = (int)((e & 4095) >> 2);

    float4 v  = ((const float4*)x)[i];
    float4 sp = ((const float4*)g_sp)[(b << 10) + hq];
    float  cw = 1.0f + __ldg(&g_chw[b * CC + c]);

    float4 o;
    o.x = v.x * (cw + sp.x);
    o.y = v.y * (cw + sp.y);
    o.z = v.z * (cw + sp.z);
    o.w = v.w * (cw + sp.w);
    ((float4*)out)[i] = o;
}

// ---------------------------------------------------------------------------
extern "C" void kernel_launch(void* const* d_in, const int* in_sizes, int n_in,
                              void* d_out, int out_size) {
    (void)in_sizes; (void)n_in; (void)out_size;
    const float* x   = (const float*)d_in[0];   // (32,256,64,64) fp32
    const float* w1  = (const float*)d_in[1];   // (1,1,5)
    const float* w2  = (const float*)d_in[2];   // (1,2,7,7)
    const float* b2  = (const float*)d_in[3];   // (1,)
    float* out = (float*)d_out;

    k1_reduce<<<BB * STRIPS, 256>>>(x);
    k23_small<<<BB * 4 + BB, 256>>>(w1, w2, b2);

    const size_t total_f4 = (size_t)BB * CC * HWN / 4;   // 8,388,608
    k4_final<<<(unsigned)(total_f4 / 256), 256>>>(x, out);
}